// round 1
// baseline (speedup 1.0000x reference)
#include <cuda_runtime.h>
#include <math.h>

#define B_ 16
#define N_ 2048
#define C_ 512
#define D_ 64

// Scratch for Q[b][n][d], K[b][n][d], V[b][n][c]  (static device globals: allowed)
__device__ float g_Q[B_ * N_ * D_];
__device__ float g_K[B_ * N_ * D_];
__device__ float g_V[B_ * N_ * C_];

// ---------------------------------------------------------------------------
// Projection GEMM: out[m, o] = sum_c X[m, c] * W[o, c] + bias[o]
// M = B*N = 32768, K = 512, Dout = 64 (Q,K) or 512 (V)
// Tile: 64 (M) x 16*KC (O), 256 threads, each thread 4 rows x KC cols.
// Smem stored k-major: Xs[kk][row], Ws[kk][o]  -> conflict-free inner loads.
// which: 0 -> g_Q, 1 -> g_K, 2 -> g_V
// ---------------------------------------------------------------------------
template <int KC>
__global__ __launch_bounds__(256) void proj_kernel(
    const float* __restrict__ X, const float* __restrict__ W,
    const float* __restrict__ bias, int which, int Dout)
{
    constexpr int TO = 16 * KC;
    __shared__ float Xs[16 * 64];
    __shared__ float Ws[16 * TO];

    float* out = (which == 0) ? g_Q : (which == 1) ? g_K : g_V;

    const int tid = threadIdx.x;
    const int tx = tid & 15, ty = tid >> 4;
    const int m0 = blockIdx.y * 64;
    const int o0 = blockIdx.x * TO;

    float acc[4][KC];
#pragma unroll
    for (int r = 0; r < 4; r++)
#pragma unroll
        for (int k = 0; k < KC; k++) acc[r][k] = 0.f;

    for (int kt = 0; kt < C_; kt += 16) {
        // X tile: 64 rows x 16 k-vals, transposed into Xs[kk][row]
        {
            int row = tid >> 2, c4 = (tid & 3) * 4;
            float4 v = *(const float4*)(X + (size_t)(m0 + row) * C_ + kt + c4);
            Xs[(c4 + 0) * 64 + row] = v.x;
            Xs[(c4 + 1) * 64 + row] = v.y;
            Xs[(c4 + 2) * 64 + row] = v.z;
            Xs[(c4 + 3) * 64 + row] = v.w;
        }
        // W tile: TO rows x 16 k-vals, transposed into Ws[kk][o]
#pragma unroll
        for (int l = 0; l < KC / 4; l++) {
            int f = tid + l * 256;
            int o = f >> 2, c4 = (f & 3) * 4;
            float4 v = *(const float4*)(W + (size_t)(o0 + o) * C_ + kt + c4);
            Ws[(c4 + 0) * TO + o] = v.x;
            Ws[(c4 + 1) * TO + o] = v.y;
            Ws[(c4 + 2) * TO + o] = v.z;
            Ws[(c4 + 3) * TO + o] = v.w;
        }
        __syncthreads();
#pragma unroll
        for (int kk = 0; kk < 16; kk++) {
            float a[4];
#pragma unroll
            for (int r = 0; r < 4; r++) a[r] = Xs[kk * 64 + 4 * ty + r];
#pragma unroll
            for (int k = 0; k < KC; k++) {
                float w = Ws[kk * TO + tx + 16 * k];
#pragma unroll
                for (int r = 0; r < 4; r++) acc[r][k] += a[r] * w;
            }
        }
        __syncthreads();
    }

#pragma unroll
    for (int k = 0; k < KC; k++) {
        int o = o0 + tx + 16 * k;
        float bvv = bias[o];
#pragma unroll
        for (int r = 0; r < 4; r++) {
            int m = m0 + 4 * ty + r;
            out[(size_t)m * Dout + o] = acc[r][k] + bvv;
        }
    }
}

// ---------------------------------------------------------------------------
// Flash attention (no 1/sqrt(d) scale, non-causal) + residual epilogue.
// Block: (cs: 1 of 4 slices of 128 V-channels, qt: 1 of 32 q-tiles of 64 rows,
//         b: batch). 256 threads; O accumulator 64x128 in registers (4x8/thr).
// Online softmax over 32 key tiles of 64.
// ---------------------------------------------------------------------------
__global__ __launch_bounds__(256, 2) void attn_kernel(
    const float* __restrict__ x, const float* __restrict__ gamma_p,
    float* __restrict__ out)
{
    extern __shared__ float sm[];
    float* Qs = sm;                  // 64*64
    float* Ks = Qs + 64 * 64;        // 64*65 (pad 1: conflict-free K reads)
    float* Ss = Ks + 64 * 65;        // 64*65
    float* Vs = Ss + 64 * 65;        // 64*128
    float* row_m = Vs + 64 * 128;    // 64
    float* row_l = row_m + 64;       // 64
    float* row_scale = row_l + 64;   // 64

    const int tid = threadIdx.x;
    const int tx = tid & 15, ty = tid >> 4;
    const int cs = blockIdx.x, qt = blockIdx.y, b = blockIdx.z;

    const float* Qg = g_Q + ((size_t)b * N_ + qt * 64) * D_;
    const float* Kg = g_K + (size_t)b * N_ * D_;
    const float* Vg = g_V + (size_t)b * N_ * C_ + cs * 128;

    // Load Q tile (64x64), stride 64 in smem
#pragma unroll
    for (int l = 0; l < 4; l++) {
        int f = tid + l * 256;
        int row = f >> 4, c4 = (f & 15) * 4;
        *(float4*)(Qs + row * 64 + c4) = *(const float4*)(Qg + row * D_ + c4);
    }
    if (tid < 64) { row_m[tid] = -INFINITY; row_l[tid] = 0.f; }

    float acc[4][8];
#pragma unroll
    for (int r = 0; r < 4; r++)
#pragma unroll
        for (int k = 0; k < 8; k++) acc[r][k] = 0.f;

    for (int mt = 0; mt < N_ / 64; mt++) {
        // K tile 64x64 -> Ks (stride 65)
#pragma unroll
        for (int l = 0; l < 4; l++) {
            int f = tid + l * 256;
            int row = f >> 4, c4 = (f & 15) * 4;
            float4 v = *(const float4*)(Kg + (size_t)(mt * 64 + row) * D_ + c4);
            float* d = Ks + row * 65 + c4;
            d[0] = v.x; d[1] = v.y; d[2] = v.z; d[3] = v.w;
        }
        // V tile 64x128 -> Vs (stride 128)
#pragma unroll
        for (int l = 0; l < 8; l++) {
            int f = tid + l * 256;
            int row = f >> 5, c4 = (f & 31) * 4;
            *(float4*)(Vs + row * 128 + c4) =
                *(const float4*)(Vg + (size_t)(mt * 64 + row) * C_ + c4);
        }
        __syncthreads();

        // S = Q * K^T : rows i = 4*ty+r, cols j = tx + 16*k
        float s[4][4];
#pragma unroll
        for (int r = 0; r < 4; r++)
#pragma unroll
            for (int k = 0; k < 4; k++) s[r][k] = 0.f;
#pragma unroll 8
        for (int d = 0; d < 64; d++) {
            float q[4];
#pragma unroll
            for (int r = 0; r < 4; r++) q[r] = Qs[(4 * ty + r) * 64 + d];
#pragma unroll
            for (int k = 0; k < 4; k++) {
                float kv = Ks[(tx + 16 * k) * 65 + d];
#pragma unroll
                for (int r = 0; r < 4; r++) s[r][k] += q[r] * kv;
            }
        }
#pragma unroll
        for (int r = 0; r < 4; r++)
#pragma unroll
            for (int k = 0; k < 4; k++)
                Ss[(4 * ty + r) * 65 + tx + 16 * k] = s[r][k];
        __syncthreads();

        // Online softmax: one thread per row (stride-65 => conflict-free)
        if (tid < 64) {
            float* Srow = Ss + tid * 65;
            float mo = row_m[tid];
            float mx = mo;
#pragma unroll 16
            for (int j = 0; j < 64; j++) mx = fmaxf(mx, Srow[j]);
            float sc = __expf(mo - mx);
            float l = row_l[tid] * sc;
#pragma unroll 16
            for (int j = 0; j < 64; j++) {
                float p = __expf(Srow[j] - mx);
                Srow[j] = p;
                l += p;
            }
            row_m[tid] = mx; row_l[tid] = l; row_scale[tid] = sc;
        }
        __syncthreads();

        // Rescale accumulator, then O += P * V
        float scr[4];
#pragma unroll
        for (int r = 0; r < 4; r++) scr[r] = row_scale[4 * ty + r];
#pragma unroll
        for (int r = 0; r < 4; r++)
#pragma unroll
            for (int k = 0; k < 8; k++) acc[r][k] *= scr[r];
#pragma unroll 4
        for (int d = 0; d < 64; d++) {
            float p[4];
#pragma unroll
            for (int r = 0; r < 4; r++) p[r] = Ss[(4 * ty + r) * 65 + d];
#pragma unroll
            for (int k = 0; k < 8; k++) {
                float v = Vs[d * 128 + tx + 16 * k];
#pragma unroll
                for (int r = 0; r < 4; r++) acc[r][k] += p[r] * v;
            }
        }
        __syncthreads();
    }

    // Epilogue: out = gamma * (O / l) + x
    const float ga = gamma_p[0];
#pragma unroll
    for (int r = 0; r < 4; r++) {
        int n = qt * 64 + 4 * ty + r;
        float inv_l = 1.f / row_l[4 * ty + r];
        size_t base = ((size_t)b * N_ + n) * C_;
#pragma unroll
        for (int k = 0; k < 8; k++) {
            int c = cs * 128 + tx + 16 * k;
            out[base + c] = ga * acc[r][k] * inv_l + x[base + c];
        }
    }
}

// ---------------------------------------------------------------------------
extern "C" void kernel_launch(void* const* d_in, const int* in_sizes, int n_in,
                              void* d_out, int out_size)
{
    const float* x     = (const float*)d_in[0];
    const float* Wq    = (const float*)d_in[1];
    const float* bq    = (const float*)d_in[2];
    const float* Wk    = (const float*)d_in[3];
    const float* bk    = (const float*)d_in[4];
    const float* Wv    = (const float*)d_in[5];
    const float* bv    = (const float*)d_in[6];
    const float* gamma = (const float*)d_in[7];
    float* out = (float*)d_out;

    const int MROWS = (B_ * N_) / 64;  // 512

    proj_kernel<4><<<dim3(1, MROWS), 256>>>(x, Wq, bq, 0, D_);
    proj_kernel<4><<<dim3(1, MROWS), 256>>>(x, Wk, bk, 1, D_);
    proj_kernel<8><<<dim3(C_ / 128, MROWS), 256>>>(x, Wv, bv, 2, C_);

    const int smem_bytes = (64 * 64 + 2 * 64 * 65 + 64 * 128 + 192) * 4; // 83200
    cudaFuncSetAttribute(attn_kernel,
                         cudaFuncAttributeMaxDynamicSharedMemorySize, smem_bytes);
    attn_kernel<<<dim3(C_ / 128, N_ / 64, B_), 256, smem_bytes>>>(x, gamma, out);
}